// round 4
// baseline (speedup 1.0000x reference)
#include <cuda_runtime.h>

// DWT_2D Haar: x (16,64,256,256) f32 -> (ll,lh,hl,hh) each (16,64,128,128).
// R4: persistent grid-stride + software pipelining (prefetch next iter's loads
// before current iter's stores) to smooth the read/write mix at the DRAM
// controllers and eliminate CTA launch/tail overhead.

#define BCN   1024
#define HDIM  256
#define WDIM  256
#define OH    128
#define OW    128

#define NTHREADS_TOTAL (1024u * 128u * 32u)   // 4,194,304 logical work items
#define GRID   2048
#define BLOCK  256
#define ITERS  8                              // 4,194,304 / (2048*256)

__device__ __forceinline__ void load_tile(unsigned tid, const float* __restrict__ x,
                                          float4& a0, float4& a1, float4& b0, float4& b1) {
    unsigned g  = tid & 31u;
    unsigned i  = (tid >> 5) & 127u;
    unsigned bc = tid >> 12;
    const float* base = x + (size_t)bc * (HDIM * WDIM) + (size_t)(2u * i) * WDIM + g * 8u;
    a0 = __ldcs((const float4*)base);
    a1 = __ldcs((const float4*)(base + 4));
    b0 = __ldcs((const float4*)(base + WDIM));
    b1 = __ldcs((const float4*)(base + WDIM + 4));
}

__device__ __forceinline__ void store_tile(unsigned tid, float* __restrict__ out,
                                           float4 a0, float4 a1, float4 b0, float4 b1) {
    float t0[8] = {a0.x, a0.y, a0.z, a0.w, a1.x, a1.y, a1.z, a1.w};
    float t1[8] = {b0.x, b0.y, b0.z, b0.w, b1.x, b1.y, b1.z, b1.w};

    float llv[4], lhv[4], hlv[4], hhv[4];
#pragma unroll
    for (int k = 0; k < 4; ++k) {
        float a = t0[2 * k], b = t0[2 * k + 1];
        float c = t1[2 * k], d = t1[2 * k + 1];
        float s0 = a + b, d0 = a - b;
        float s1 = c + d, d1 = c - d;
        llv[k] = 0.5f * (s0 + s1);
        lhv[k] = 0.5f * (d0 + d1);
        hlv[k] = 0.5f * (s0 - s1);
        hhv[k] = 0.5f * (d0 - d1);
    }

    unsigned g  = tid & 31u;
    unsigned i  = (tid >> 5) & 127u;
    unsigned bc = tid >> 12;
    const size_t band = (size_t)BCN * OH * OW;
    size_t o = (size_t)bc * (OH * OW) + (size_t)i * OW + g * 4u;

    __stcs((float4*)(out + o),            make_float4(llv[0], llv[1], llv[2], llv[3]));
    __stcs((float4*)(out + band + o),     make_float4(lhv[0], lhv[1], lhv[2], lhv[3]));
    __stcs((float4*)(out + 2 * band + o), make_float4(hlv[0], hlv[1], hlv[2], hlv[3]));
    __stcs((float4*)(out + 3 * band + o), make_float4(hhv[0], hhv[1], hhv[2], hhv[3]));
}

__global__ void __launch_bounds__(BLOCK)
dwt2d_haar_kernel(const float* __restrict__ x, float* __restrict__ out) {
    const unsigned stride = GRID * BLOCK;            // 524,288
    unsigned tid = blockIdx.x * BLOCK + threadIdx.x;

    // Prologue: loads for iteration 0
    float4 ca0, ca1, cb0, cb1;
    load_tile(tid, x, ca0, ca1, cb0, cb1);

#pragma unroll
    for (int it = 0; it < ITERS; ++it) {
        float4 na0, na1, nb0, nb1;
        unsigned ntid = tid + stride;
        if (it < ITERS - 1) {
            // Prefetch next iteration's 4x LDG.128 BEFORE this iteration's stores:
            // keeps reads and writes simultaneously in flight per SM.
            load_tile(ntid, x, na0, na1, nb0, nb1);
        }
        store_tile(tid, out, ca0, ca1, cb0, cb1);
        ca0 = na0; ca1 = na1; cb0 = nb0; cb1 = nb1;
        tid = ntid;
    }
}

extern "C" void kernel_launch(void* const* d_in, const int* in_sizes, int n_in,
                              void* d_out, int out_size) {
    const float* x = (const float*)d_in[0];
    float* out = (float*)d_out;
    dwt2d_haar_kernel<<<GRID, BLOCK>>>(x, out);
}

// round 5
// speedup vs baseline: 1.0203x; 1.0203x over previous
#include <cuda_runtime.h>

// DWT_2D Haar: x (16,64,256,256) f32 -> (ll,lh,hl,hh) each (16,64,128,128).
// Final: smem-staged band-contiguous writes (best bench variant), default
// cached loads, streaming (.cs) stores. Kernel is DRAM-saturated at the
// measured ~6.4 TB/s mixed R/W ceiling (80% of 8 TB/s spec); traffic is
// compulsory (536 MB), so this sits at the machine floor.

#define BCN   1024
#define HDIM  256
#define WDIM  256
#define OH    128
#define OW    128

__global__ void __launch_bounds__(256)
dwt2d_haar_kernel(const float* __restrict__ x, float* __restrict__ out) {
    __shared__ float4 stage[4][256];   // [band][orow*32 + g] -> 16KB

    unsigned b    = blockIdx.x;
    unsigned bc   = b >> 4;            // (b*c) slice, 0..1023
    unsigned rblk = b & 15u;           // 8-output-row block within slice

    unsigned t    = threadIdx.x;
    unsigned g    = t & 31u;           // 4 output cols (8 input cols)
    unsigned orow = t >> 5;            // 0..7

    // ---- compute: butterfly on one row-pair segment ----
    unsigned irow = (rblk * 8u + orow) * 2u;
    const float* base = x + (size_t)bc * (HDIM * WDIM) + (size_t)irow * WDIM + g * 8u;

    float4 r0a = *(const float4*)base;
    float4 r0b = *(const float4*)(base + 4);
    float4 r1a = *(const float4*)(base + WDIM);
    float4 r1b = *(const float4*)(base + WDIM + 4);

    float t0[8] = {r0a.x, r0a.y, r0a.z, r0a.w, r0b.x, r0b.y, r0b.z, r0b.w};
    float t1[8] = {r1a.x, r1a.y, r1a.z, r1a.w, r1b.x, r1b.y, r1b.z, r1b.w};

    float llv[4], lhv[4], hlv[4], hhv[4];
#pragma unroll
    for (int k = 0; k < 4; ++k) {
        float a = t0[2 * k], bb = t0[2 * k + 1];
        float c = t1[2 * k], d  = t1[2 * k + 1];
        float s0 = a + bb, d0 = a - bb;
        float s1 = c + d,  d1 = c - d;
        llv[k] = 0.5f * (s0 + s1);
        lhv[k] = 0.5f * (d0 + d1);
        hlv[k] = 0.5f * (s0 - s1);
        hhv[k] = 0.5f * (d0 - d1);
    }

    unsigned e = orow * 32u + g;
    stage[0][e] = make_float4(llv[0], llv[1], llv[2], llv[3]);
    stage[1][e] = make_float4(lhv[0], lhv[1], lhv[2], lhv[3]);
    stage[2][e] = make_float4(hlv[0], hlv[1], hlv[2], hlv[3]);
    stage[3][e] = make_float4(hhv[0], hhv[1], hhv[2], hhv[3]);

    __syncthreads();

    // ---- write: warp w -> band w/2, half w%2; 4KB contiguous per band ----
    unsigned w    = t >> 5;
    unsigned lane = t & 31u;
    unsigned band = w >> 1;
    unsigned half = w & 1u;

    const size_t bandstride = (size_t)BCN * OH * OW;
    float4* dst = (float4*)(out + band * bandstride
                                + (size_t)bc * (OH * OW)
                                + (size_t)(rblk * 8u) * OW);

#pragma unroll
    for (int k = 0; k < 4; ++k) {
        unsigned idx = half * 128u + (unsigned)k * 32u + lane;  // 0..255
        __stcs(dst + idx, stage[band][idx]);
    }
}

extern "C" void kernel_launch(void* const* d_in, const int* in_sizes, int n_in,
                              void* d_out, int out_size) {
    const float* x = (const float*)d_in[0];
    float* out = (float*)d_out;
    dwt2d_haar_kernel<<<16384, 256>>>(x, out);
}